// round 8
// baseline (speedup 1.0000x reference)
#include <cuda_runtime.h>

#define DATA_NUM 1024
#define CLS_NUM  32000
#define NB       4096            // histogram bins (both levels)
#define NT       256             // threads per CTA
#define BPT      (NB / NT)       // 16 bins per thread
#define RANGE_L  96.0f           // logit window below the M2 bound

// Guaranteed-scalar 32-bit global load (volatile is never vector-merged).
__device__ __forceinline__ float vload(const float* p) {
    return *(const volatile float*)p;
}

// Block-wide sum via plain shared-memory tree (no shuffles). red: NT floats.
__device__ float block_sum(float v, float* red) {
    int tid = threadIdx.x;
    __syncthreads();                 // protect red from prior use
    red[tid] = v;
    __syncthreads();
#pragma unroll
    for (int s = NT / 2; s > 0; s >>= 1) {
        if (tid < s) red[tid] += red[tid + s];
        __syncthreads();
    }
    float r = red[0];
    __syncthreads();
    return r;
}

// Find bin where ascending cumulative mass crosses `target`.
// *s_bin = crossing bin, *s_cdf = exclusive prefix mass of that bin.
// Sequential tid0 scan over NT partials; no shuffles. Ends synced.
__device__ void find_crossing(const float* hist, float* red, float target,
                              int* s_bin, float* s_cdf) {
    int tid = threadIdx.x;
    __syncthreads();
    if (tid == 0) { *s_bin = NB - 1; *s_cdf = 0.f; }   // safe default
    float h[BPT];
    float s = 0.f;
    const volatile float* vh = hist;
#pragma unroll
    for (int i = 0; i < BPT; i++) { h[i] = vh[tid * BPT + i]; s += h[i]; }
    red[tid] = s;
    __syncthreads();
    if (tid == 0) {                  // exclusive scan of NT partials
        float c = 0.f;
        for (int i = 0; i < NT; i++) { float t = red[i]; red[i] = c; c += t; }
    }
    __syncthreads();
    float c = red[tid];
#pragma unroll
    for (int i = 0; i < BPT; i++) {
        if (c < target && c + h[i] >= target) { *s_bin = tid * BPT + i; *s_cdf = c; }
        c += h[i];
    }
    __syncthreads();
}

// ---------------------------------------------------------------------------
__global__ void zero_out(float* out) { out[0] = 0.f; }

// One CTA per data row. Static smem only; no device symbols; no shuffles.
__global__ void __launch_bounds__(NT, 1) akl_kernel(
    const float* h1, const float* e1,
    const float* h3, const float* e3, float* out)
{
    __shared__ float hist[NB];
    __shared__ float red[NT];
    __shared__ float s_cdf1, s_cdf2;
    __shared__ int   s_b1,   s_b2;

    const int row = blockIdx.x;
    const int tid = threadIdx.x;

    const float a1 = vload(h1 + 2 * row), b1c = vload(h1 + 2 * row + 1);
    const float a3 = vload(h3 + 2 * row), b3c = vload(h3 + 2 * row + 1);
    // Analytic logit upper bounds: |l| <= ||h_row|| * max||e_j||, and the max
    // 2-D standard-normal norm over 32000 draws is < 6 w.o.p. Softmax is
    // shift-invariant, so any valid bound gives exact math (no overflow).
    const float M1 = 6.0f * sqrtf(a1 * a1 + b1c * b1c);
    const float M2 = 6.0f * sqrtf(a3 * a3 + b3c * b3c);
    const float lo   = M2 - RANGE_L;
    const float invw = (float)NB / RANGE_L;

    for (int b = tid; b < NB; b += NT) hist[b] = 0.f;
    __syncthreads();

    // ---- Pass 1: partition sums, KL linear terms, level-1 histogram of u2
    float Z1 = 0.f, Z2 = 0.f, S1 = 0.f, S2 = 0.f;
    for (int j = tid; j < CLS_NUM; j += NT) {
        float v1x = vload(e1 + 2 * j), v1y = vload(e1 + 2 * j + 1);
        float v3x = vload(e3 + 2 * j), v3y = vload(e3 + 2 * j + 1);
        float l1 = fmaf(a1, v1x, b1c * v1y);
        float l2 = fmaf(a3, v3x, b3c * v3y);
        float u1 = __expf(l1 - M1);
        float u2 = __expf(l2 - M2);
        Z1 += u1; Z2 += u2;
        float dl = l2 - l1;
        S2 = fmaf(u2,  dl, S2);
        S1 = fmaf(u1, -dl, S1);
        int b = (int)((l2 - lo) * invw);
        b = max(0, min(NB - 1, b));
        atomicAdd(&hist[b], u2);
    }
    Z1 = block_sum(Z1, red);
    Z2 = block_sum(Z2, red);
    S1 = block_sum(S1, red);
    S2 = block_sum(S2, red);
    const float halfZ2 = 0.5f * Z2;

    // ---- Level-1 crossing bin
    find_crossing(hist, red, halfZ2, &s_b1, &s_cdf1);
    const int   b1   = s_b1;
    const float cdf1 = s_cdf1;
    __syncthreads();

    // ---- Level-2: refine inside the crossing bin (recompute l2 from e3)
    const float w1    = RANGE_L / (float)NB;
    const float lo1   = lo + (float)b1 * w1;
    const float invw2 = (float)NB / w1;

    for (int b = tid; b < NB; b += NT) hist[b] = 0.f;
    __syncthreads();
    for (int j = tid; j < CLS_NUM; j += NT) {
        float v3x = vload(e3 + 2 * j), v3y = vload(e3 + 2 * j + 1);
        float l2 = fmaf(a3, v3x, b3c * v3y);
        int b = (int)((l2 - lo) * invw);
        b = max(0, min(NB - 1, b));
        if (b == b1) {
            int s = (int)((l2 - lo1) * invw2);
            s = max(0, min(NB - 1, s));
            atomicAdd(&hist[s], __expf(l2 - M2));
        }
    }
    find_crossing(hist, red, halfZ2 - cdf1, &s_b2, &s_cdf2);
    const int   b2   = s_b2;
    const float cdf2 = cdf1 + s_cdf2;   // mass strictly below the final sub-bin
    __syncthreads();

    // ---- Pass 3: head/tail gap sums (recompute both logits)
    const float invZ1 = 1.0f / Z1, invZ2 = 1.0f / Z2;
    float gh = 0.f, gt = 0.f;
    for (int j = tid; j < CLS_NUM; j += NT) {
        float v1x = vload(e1 + 2 * j), v1y = vload(e1 + 2 * j + 1);
        float v3x = vload(e3 + 2 * j), v3y = vload(e3 + 2 * j + 1);
        float l1 = fmaf(a1, v1x, b1c * v1y);
        float l2 = fmaf(a3, v3x, b3c * v3y);
        float u2 = __expf(l2 - M2);
        float p1 = __expf(l1 - M1) * invZ1;
        float p2 = u2 * invZ2;
        float gap = fabsf(p2 - p1);
        int b = (int)((l2 - lo) * invw);
        b = max(0, min(NB - 1, b));
        bool tail;
        if (b != b1) {
            tail = (b < b1);
        } else {
            int s = (int)((l2 - lo1) * invw2);
            s = max(0, min(NB - 1, s));
            if (s != b2) tail = (s < b2);
            else         tail = (cdf2 + u2) < halfZ2;
        }
        if (tail) gt += gap; else gh += gap;
    }
    gh = block_sum(gh, red);
    gt = block_sum(gt, red);

    if (tid == 0) {
        // fkl = S2/Z2 - C21 ; rkl = S1/Z1 + C21   (C21 = logZ2+M2 - logZ1-M1)
        float C21 = (M2 + __logf(Z2)) - (M1 + __logf(Z1));
        float fkl = S2 / Z2 - C21;
        float rkl = S1 / Z1 + C21;
        float denom = gh + gt;
        float akl = (gh * fkl + gt * rkl) / denom;
        atomicAdd(out, akl * (1.0f / (float)DATA_NUM));
    }
}

// ---------------------------------------------------------------------------
extern "C" void kernel_launch(void* const* d_in, const int* in_sizes, int n_in,
                              void* d_out, int out_size) {
    // Bind by size (element OR byte counts); positional fallback.
    const float *h1 = 0, *h3 = 0, *e1 = 0, *e3 = 0;
    for (int i = 0; i < n_in; i++) {
        int s = in_sizes[i];
        if (s == 2 * DATA_NUM || s == 2 * DATA_NUM * 4) {
            if (!h1) h1 = (const float*)d_in[i]; else if (!h3) h3 = (const float*)d_in[i];
        } else if (s == 2 * CLS_NUM || s == 2 * CLS_NUM * 4) {
            if (!e1) e1 = (const float*)d_in[i]; else if (!e3) e3 = (const float*)d_in[i];
        }
    }
    if (!h1 || !h3 || !e1 || !e3) {
        h1 = (const float*)d_in[0];
        e1 = (const float*)d_in[1];
        h3 = (const float*)d_in[2];
        e3 = (const float*)d_in[3];
    }

    float* out = (float*)d_out;
    zero_out<<<1, 1>>>(out);
    akl_kernel<<<DATA_NUM, NT>>>(h1, e1, h3, e3, out);
}